// round 14
// baseline (speedup 1.0000x reference)
#include <cuda_runtime.h>
#include <cuda_fp16.h>
#include <cstdint>
#include <math.h>

#define BB 512
#define RR 1152
#define OO 16
#define CO 160
#define II 8
#define CHUNK 8
#define NCHUNK (RR / CHUNK)     // 144
#define HALFCH (NCHUNK / 2)     // 72 chunks per cluster-CTA
#define ITERS2 (HALFCH / 8)     // 9 chunk-iterations per warp

// u_hat fp16 [b][r][co], 189 MB (sanctioned __device__ scratch)
__device__ uint4 g_uhat4[(size_t)BB * RR * CO / 8];

// ---------------------------------------------------------------------------
// K1: u_hat[b,r,:] = W[r]·x[b,r] in fp16 (HFMA2), stored half2. (Proven R9.)
// ---------------------------------------------------------------------------
__global__ __launch_bounds__(256) void uhat_kernel(const float* __restrict__ x,
                                                   const float* __restrict__ W) {
    const int r = blockIdx.x;
    const int tid = threadIdx.x;
    const int w = tid >> 5;
    const int l = tid & 31;

    __shared__ __half2 xs2[BB * II];  // 16 KB: (x_i, x_i) per (b,i)

    for (int idx = tid; idx < BB * 2; idx += 256) {
        int b = idx >> 1, part = idx & 1;
        float4 v = reinterpret_cast<const float4*>(x)[(size_t)b * (RR * 2) + r * 2 + part];
        int base = b * 8 + part * 4;
        xs2[base + 0] = __half2half2(__float2half_rn(v.x));
        xs2[base + 1] = __half2half2(__float2half_rn(v.y));
        xs2[base + 2] = __half2half2(__float2half_rn(v.z));
        xs2[base + 3] = __half2half2(__float2half_rn(v.w));
    }

    const float* Wr = W + (size_t)r * CO * II;
    __half2 wh[3][8];
#pragma unroll
    for (int s = 0; s < 3; s++) {
        if (s < 2 || l < 16) {
            int p = s * 32 + l;
            const float4* A = reinterpret_cast<const float4*>(Wr + (2 * p) * II);
            const float4* B = reinterpret_cast<const float4*>(Wr + (2 * p + 1) * II);
            float4 a0 = A[0], a1 = A[1], b0 = B[0], b1 = B[1];
            wh[s][0] = __floats2half2_rn(a0.x, b0.x);
            wh[s][1] = __floats2half2_rn(a0.y, b0.y);
            wh[s][2] = __floats2half2_rn(a0.z, b0.z);
            wh[s][3] = __floats2half2_rn(a0.w, b0.w);
            wh[s][4] = __floats2half2_rn(a1.x, b1.x);
            wh[s][5] = __floats2half2_rn(a1.y, b1.y);
            wh[s][6] = __floats2half2_rn(a1.z, b1.z);
            wh[s][7] = __floats2half2_rn(a1.w, b1.w);
        }
    }
    __syncthreads();

    for (int b = w; b < BB; b += 8) {
        uint4 xv0 = *reinterpret_cast<const uint4*>(&xs2[b * 8]);
        uint4 xv1 = *reinterpret_cast<const uint4*>(&xs2[b * 8 + 4]);
        __half2 xh[8];
        {
            const __half2* p0 = reinterpret_cast<const __half2*>(&xv0);
            const __half2* p1 = reinterpret_cast<const __half2*>(&xv1);
#pragma unroll
            for (int i = 0; i < 4; i++) { xh[i] = p0[i]; xh[4 + i] = p1[i]; }
        }
        __half2* outp = reinterpret_cast<__half2*>(g_uhat4 + ((size_t)b * RR + r) * (CO / 8));
#pragma unroll
        for (int s = 0; s < 3; s++) {
            if (s < 2 || l < 16) {
                __half2 aA = __hmul2(wh[s][0], xh[0]);
                __half2 aB = __hmul2(wh[s][1], xh[1]);
                aA = __hfma2(wh[s][2], xh[2], aA);
                aB = __hfma2(wh[s][3], xh[3], aB);
                aA = __hfma2(wh[s][4], xh[4], aA);
                aB = __hfma2(wh[s][5], xh[5], aB);
                aA = __hfma2(wh[s][6], xh[6], aA);
                aB = __hfma2(wh[s][7], xh[7], aB);
                outp[s * 32 + l] = __hadd2(aA, aB);
            }
        }
    }
}

// ---------------------------------------------------------------------------
// Fused routing, cluster-2 per b. R14: smem diet for occupancy — 2-stage
// cp.async ring (40KB) and the 40KB f32 flush buffer ALIASED onto the ring
// (only live post-chunks; extra __syncthreads makes the overlap safe).
// Total smem 43.4KB -> 5 CTAs/SM (was 2), 10 warps/SMSP to hide the
// LDS/SHFL/MUFU chains that capped issue at 35%.
// Shuffle-resident softmax lane mapping (proven R13):
//   lane l: row=l>>2, q=l&3, h=q&1 (o-half), c0=q>>1; k-th uint4: c=c0+2k.
//   round 0: c uniform (=0.1) -> v0
//   round 1: logits = u.v0    -> vacc = v0 + v1
//   round 2: logits = u.vacc  -> v2 -> dout (rank 0 writes)
// ---------------------------------------------------------------------------

// smem byte offsets (part ALIASES the 2-stage ring)
#define RING_OFF 0                          // uint4[2][8][160] = 40960
#define PART_OFF 0                          // f32[8][8][160]   = 40960 (alias)
#define SLOT_OFF 40960                      // f32[2][2][160] = 2560
#define VACC_OFF 43520                      // f32[160] = 640
#define VH_OFF   44160                      // u32[80] = 320
#define SMEM_BYTES 44480
#define STAGE_B 20480                       // bytes per ring stage

__device__ __forceinline__ void st_peer_f32(unsigned int laddr, unsigned int peer, float v) {
    asm volatile(
        "{ .reg .b32 ra; mapa.shared::cluster.u32 ra, %0, %1; "
        "st.shared::cluster.f32 [ra], %2; }"
        :: "r"(laddr), "r"(peer), "f"(v) : "memory");
}
__device__ __forceinline__ void cp16(unsigned int dst, const void* src) {
    asm volatile("cp.async.cg.shared.global [%0], [%1], 16;" :: "r"(dst), "l"(src) : "memory");
}
__device__ __forceinline__ void cp_commit() {
    asm volatile("cp.async.commit_group;" ::: "memory");
}
__device__ __forceinline__ void cp_wait1() {
    asm volatile("cp.async.wait_group 1;" ::: "memory");
}

__global__ __launch_bounds__(256, 2) __cluster_dims__(2, 1, 1)
void route3_kernel(const float* __restrict__ bias, float* __restrict__ dout) {
    extern __shared__ char sm[];
    uint4* ring = reinterpret_cast<uint4*>(sm + RING_OFF);
    float* part = reinterpret_cast<float*>(sm + PART_OFF);   // alias of ring
    float* slot = reinterpret_cast<float*>(sm + SLOT_OFF);
    float* vacc = reinterpret_cast<float*>(sm + VACC_OFF);
    unsigned int* vh = reinterpret_cast<unsigned int*>(sm + VH_OFF);

    const int tid = threadIdx.x;
    const int w = tid >> 5;
    const int l = tid & 31;
    const int rowl = l >> 2;      // row within chunk (0..7)
    const int q = l & 3;
    const int h = q & 1;          // o-half
    const int c0 = q >> 1;        // capsule parity
    const int b = blockIdx.x >> 1;
    unsigned int rank;
    asm("mov.u32 %0, %%cluster_ctarank;" : "=r"(rank));

    // lane's 5 uint4 slots within a chunk: idx = rowl*20 + q + 4k
    const int lane_u4 = rowl * 20 + q;
    const unsigned int ring0 = (unsigned int)__cvta_generic_to_shared(ring);
    const unsigned int lane_b = (unsigned int)(w * 160 + lane_u4) * 16;

    // v addresses: k-th capsule c=c0+2k, half h -> vh half2 index (c*8 + h*4)
    unsigned int vaddr[5];
#pragma unroll
    for (int k = 0; k < 5; k++)
        vaddr[k] = (unsigned int)__cvta_generic_to_shared(&vh[(c0 + 2 * k) * 8 + h * 4]);

    const uint4* ubase = g_uhat4 + ((size_t)b * RR + rank * (HALFCH * CHUNK)) * (CO / 8);

    for (int round = 0; round < 3; round++) {
        __half2 accA[5][4], accB[5][4];
        const __half2 hz = __float2half2_rn(0.0f);
#pragma unroll
        for (int k = 0; k < 5; k++)
#pragma unroll
            for (int kk = 0; kk < 4; kk++) { accA[k][kk] = hz; accB[k][kk] = hz; }

        // prologue: stages 0..1 <- chunks 0..1
#pragma unroll
        for (int pf = 0; pf < 2; pf++) {
            const uint4* src = ubase + (w + pf * 8) * (CHUNK * CO / 8) + lane_u4;
            unsigned int dst = ring0 + pf * STAGE_B + lane_b;
#pragma unroll
            for (int k = 0; k < 5; k++) cp16(dst + k * 64, src + 4 * k);
            cp_commit();
        }

#pragma unroll
        for (int it = 0; it < ITERS2; it++) {  // 9, fully unrolled
            const int stage = it & 1;          // compile-time
            cp_wait1();

            uint4 uu[5];
            const uint4* rs = ring + stage * 1280 + (w * 160 + lane_u4);
#pragma unroll
            for (int k = 0; k < 5; k++) uu[k] = rs[4 * k];

            __half2 wgt2[5];
            if (round > 0) {
                float e[5];
#pragma unroll
                for (int k = 0; k < 5; k++) {
                    unsigned int v0r, v1r, v2r, v3r;
                    asm volatile("ld.shared.v4.b32 {%0,%1,%2,%3},[%4];"
                                 : "=r"(v0r), "=r"(v1r), "=r"(v2r), "=r"(v3r)
                                 : "r"(vaddr[k]));
                    const __half2* u2 = reinterpret_cast<const __half2*>(&uu[k]);
                    __half2 p2 = __hmul2(u2[0], *reinterpret_cast<__half2*>(&v0r));
                    p2 = __hfma2(u2[1], *reinterpret_cast<__half2*>(&v1r), p2);
                    p2 = __hfma2(u2[2], *reinterpret_cast<__half2*>(&v2r), p2);
                    p2 = __hfma2(u2[3], *reinterpret_cast<__half2*>(&v3r), p2);
                    float own = __low2float(p2) + __high2float(p2);
                    // join o-halves: partner lane l^1 has same capsule, other half
                    float lg = own + __shfl_xor_sync(0xffffffffu, own, 1);
                    e[k] = __expf(lg);  // logits bounded; no max-sub needed
                }
                // softmax over 10 capsules: own 5 (same parity) + partner parity
                float s5 = e[0] + e[1] + e[2] + e[3] + e[4];
                float tot = s5 + __shfl_xor_sync(0xffffffffu, s5, 2);
                float inv = 1.0f / tot;
#pragma unroll
                for (int k = 0; k < 5; k++)
                    wgt2[k] = __half2half2(__float2half_rn(e[k] * inv));
            }

            if ((it & 1) == 0) {  // static parity -> accA
#pragma unroll
                for (int k = 0; k < 5; k++) {
                    const __half2* u2 = reinterpret_cast<const __half2*>(&uu[k]);
                    if (round == 0) {
#pragma unroll
                        for (int kk = 0; kk < 4; kk++) accA[k][kk] = __hadd2(accA[k][kk], u2[kk]);
                    } else {
#pragma unroll
                        for (int kk = 0; kk < 4; kk++) accA[k][kk] = __hfma2(u2[kk], wgt2[k], accA[k][kk]);
                    }
                }
            } else {              // -> accB
#pragma unroll
                for (int k = 0; k < 5; k++) {
                    const __half2* u2 = reinterpret_cast<const __half2*>(&uu[k]);
                    if (round == 0) {
#pragma unroll
                        for (int kk = 0; kk < 4; kk++) accB[k][kk] = __hadd2(accB[k][kk], u2[kk]);
                    } else {
#pragma unroll
                        for (int kk = 0; kk < 4; kk++) accB[k][kk] = __hfma2(u2[kk], wgt2[k], accB[k][kk]);
                    }
                }
            }

            // refill this stage with chunk it+2 (compile-time guard)
            if (it + 2 < ITERS2) {
                const uint4* src = ubase + (w + (it + 2) * 8) * (CHUNK * CO / 8) + lane_u4;
                unsigned int dst = ring0 + stage * STAGE_B + lane_b;
#pragma unroll
                for (int k = 0; k < 5; k++) cp16(dst + k * 64, src + 4 * k);
            }
            cp_commit();
        }

        // all warps done with ring reads before part (ring alias) is written
        __syncthreads();

        // flush dual fp16 accumulators to f32 partials (once per round)
        // lane owns co = (c0+2k)*16 + h*8 + [0,8)
#pragma unroll
        for (int k = 0; k < 5; k++) {
            float* pj = part + (w * 8 + rowl) * CO + (c0 + 2 * k) * 16 + h * 8;
#pragma unroll
            for (int kk = 0; kk < 4; kk++) {
                float2 fa = __half22float2(accA[k][kk]);
                float2 fb = __half22float2(accB[k][kk]);
                pj[2 * kk]     = fa.x + fb.x;
                pj[2 * kk + 1] = fa.y + fb.y;
            }
        }
        __syncthreads();

        const int buf = round & 1;
        if (tid < CO) {
            float s = 0.0f;
#pragma unroll
            for (int i = 0; i < 64; i++) s += part[i * CO + tid];
            slot[(buf * 2 + rank) * CO + tid] = s;  // local copy
            unsigned int laddr = (unsigned int)__cvta_generic_to_shared(&slot[(buf * 2 + rank) * CO + tid]);
            st_peer_f32(laddr, rank ^ 1u, s);       // peer copy
        }
        asm volatile("barrier.cluster.arrive.aligned;" ::: "memory");
        asm volatile("barrier.cluster.wait.aligned;" ::: "memory");

        if (tid < CO) {
            float s = slot[(buf * 2 + 0) * CO + tid] + slot[(buf * 2 + 1) * CO + tid];
            if (round == 0) s *= 0.1f;  // softmax(0) = 1/10 exactly
            s += bias[tid];
            part[tid] = s;
        }
        __syncthreads();

        if (tid < CO) {
            int c = tid >> 4;
            float nsq = 0.0f;
#pragma unroll
            for (int o = 0; o < OO; o++) {
                float t = part[c * OO + o];
                nsq += t * t;
            }
            float val = part[tid] * (sqrtf(nsq) / (1.0f + nsq + 1e-8f));
            if (round == 0) vacc[tid] = val;                 // v0
            else if (round == 1) vacc[tid] += val;           // v0 + v1
            else if (rank == 0) dout[b * CO + tid] = val;    // v2 (final)
        }
        __syncthreads();

        if (round < 2 && tid < 80) {
            __half2 hv = __floats2half2_rn(vacc[2 * tid], vacc[2 * tid + 1]);
            vh[tid] = *reinterpret_cast<unsigned int*>(&hv);
        }
        __syncthreads();
    }
}

// ---------------------------------------------------------------------------
extern "C" void kernel_launch(void* const* d_in, const int* in_sizes, int n_in,
                              void* d_out, int out_size) {
    const float* x    = (const float*)d_in[0];  // [512,1152,8]
    const float* W    = (const float*)d_in[1];  // [1152,10,16,8]
    const float* bias = (const float*)d_in[2];  // [1,1,10,16]
    float* out = (float*)d_out;                 // [512,10,16]

    cudaFuncSetAttribute(route3_kernel, cudaFuncAttributeMaxDynamicSharedMemorySize, SMEM_BYTES);

    uhat_kernel<<<RR, 256>>>(x, W);
    route3_kernel<<<BB * 2, 256, SMEM_BYTES>>>(bias, out);
}

// round 15
// speedup vs baseline: 1.0812x; 1.0812x over previous
#include <cuda_runtime.h>
#include <cuda_fp16.h>
#include <cstdint>
#include <math.h>

#define BB 512
#define RR 1152
#define OO 16
#define CO 160
#define II 8
#define CHUNK 8
#define NCHUNK (RR / CHUNK)     // 144
#define HALFCH (NCHUNK / 2)     // 72 chunks per cluster-CTA
#define ITERS2 (HALFCH / 8)     // 9 chunk-iterations per warp

// u_hat fp16 [b][r][co], 189 MB (sanctioned __device__ scratch)
__device__ uint4 g_uhat4[(size_t)BB * RR * CO / 8];

// ---------------------------------------------------------------------------
// K1: u_hat[b,r,:] = W[r]·x[b,r] in fp16 (HFMA2), stored half2. (Proven R9.)
// ---------------------------------------------------------------------------
__global__ __launch_bounds__(256) void uhat_kernel(const float* __restrict__ x,
                                                   const float* __restrict__ W) {
    const int r = blockIdx.x;
    const int tid = threadIdx.x;
    const int w = tid >> 5;
    const int l = tid & 31;

    __shared__ __half2 xs2[BB * II];  // 16 KB: (x_i, x_i) per (b,i)

    for (int idx = tid; idx < BB * 2; idx += 256) {
        int b = idx >> 1, part = idx & 1;
        float4 v = reinterpret_cast<const float4*>(x)[(size_t)b * (RR * 2) + r * 2 + part];
        int base = b * 8 + part * 4;
        xs2[base + 0] = __half2half2(__float2half_rn(v.x));
        xs2[base + 1] = __half2half2(__float2half_rn(v.y));
        xs2[base + 2] = __half2half2(__float2half_rn(v.z));
        xs2[base + 3] = __half2half2(__float2half_rn(v.w));
    }

    const float* Wr = W + (size_t)r * CO * II;
    __half2 wh[3][8];
#pragma unroll
    for (int s = 0; s < 3; s++) {
        if (s < 2 || l < 16) {
            int p = s * 32 + l;
            const float4* A = reinterpret_cast<const float4*>(Wr + (2 * p) * II);
            const float4* B = reinterpret_cast<const float4*>(Wr + (2 * p + 1) * II);
            float4 a0 = A[0], a1 = A[1], b0 = B[0], b1 = B[1];
            wh[s][0] = __floats2half2_rn(a0.x, b0.x);
            wh[s][1] = __floats2half2_rn(a0.y, b0.y);
            wh[s][2] = __floats2half2_rn(a0.z, b0.z);
            wh[s][3] = __floats2half2_rn(a0.w, b0.w);
            wh[s][4] = __floats2half2_rn(a1.x, b1.x);
            wh[s][5] = __floats2half2_rn(a1.y, b1.y);
            wh[s][6] = __floats2half2_rn(a1.z, b1.z);
            wh[s][7] = __floats2half2_rn(a1.w, b1.w);
        }
    }
    __syncthreads();

    for (int b = w; b < BB; b += 8) {
        uint4 xv0 = *reinterpret_cast<const uint4*>(&xs2[b * 8]);
        uint4 xv1 = *reinterpret_cast<const uint4*>(&xs2[b * 8 + 4]);
        __half2 xh[8];
        {
            const __half2* p0 = reinterpret_cast<const __half2*>(&xv0);
            const __half2* p1 = reinterpret_cast<const __half2*>(&xv1);
#pragma unroll
            for (int i = 0; i < 4; i++) { xh[i] = p0[i]; xh[4 + i] = p1[i]; }
        }
        __half2* outp = reinterpret_cast<__half2*>(g_uhat4 + ((size_t)b * RR + r) * (CO / 8));
#pragma unroll
        for (int s = 0; s < 3; s++) {
            if (s < 2 || l < 16) {
                __half2 aA = __hmul2(wh[s][0], xh[0]);
                __half2 aB = __hmul2(wh[s][1], xh[1]);
                aA = __hfma2(wh[s][2], xh[2], aA);
                aB = __hfma2(wh[s][3], xh[3], aB);
                aA = __hfma2(wh[s][4], xh[4], aA);
                aB = __hfma2(wh[s][5], xh[5], aB);
                aA = __hfma2(wh[s][6], xh[6], aA);
                aB = __hfma2(wh[s][7], xh[7], aB);
                outp[s * 32 + l] = __hadd2(aA, aB);
            }
        }
    }
}

// ---------------------------------------------------------------------------
// Fused routing, cluster-2 per b. R15: unlock 3 CTAs/SM — single fp16
// accumulator (saves 20 regs vs dual; depth 9, error budget checked) +
// __launch_bounds__(256,3) to pin regs <= 85; smem stays on the R14 diet
// (2-stage ring, part aliased, 44.5KB -> 3 CTAs fit 232KB/SM).
// Shuffle-resident softmax lane mapping (proven R13):
//   lane l: row=l>>2, q=l&3, h=q&1 (o-half), c0=q>>1; k-th uint4: c=c0+2k.
//   round 0: c uniform (=0.1) -> v0
//   round 1: logits = u.v0    -> vacc = v0 + v1
//   round 2: logits = u.vacc  -> v2 -> dout (rank 0 writes)
// ---------------------------------------------------------------------------

// smem byte offsets (part ALIASES the 2-stage ring)
#define RING_OFF 0                          // uint4[2][8][160] = 40960
#define PART_OFF 0                          // f32[8][8][160]   = 40960 (alias)
#define SLOT_OFF 40960                      // f32[2][2][160] = 2560
#define VACC_OFF 43520                      // f32[160] = 640
#define VH_OFF   44160                      // u32[80] = 320
#define SMEM_BYTES 44480
#define STAGE_B 20480                       // bytes per ring stage

__device__ __forceinline__ void st_peer_f32(unsigned int laddr, unsigned int peer, float v) {
    asm volatile(
        "{ .reg .b32 ra; mapa.shared::cluster.u32 ra, %0, %1; "
        "st.shared::cluster.f32 [ra], %2; }"
        :: "r"(laddr), "r"(peer), "f"(v) : "memory");
}
__device__ __forceinline__ void cp16(unsigned int dst, const void* src) {
    asm volatile("cp.async.cg.shared.global [%0], [%1], 16;" :: "r"(dst), "l"(src) : "memory");
}
__device__ __forceinline__ void cp_commit() {
    asm volatile("cp.async.commit_group;" ::: "memory");
}
__device__ __forceinline__ void cp_wait1() {
    asm volatile("cp.async.wait_group 1;" ::: "memory");
}

__global__ __launch_bounds__(256, 3) __cluster_dims__(2, 1, 1)
void route3_kernel(const float* __restrict__ bias, float* __restrict__ dout) {
    extern __shared__ char sm[];
    uint4* ring = reinterpret_cast<uint4*>(sm + RING_OFF);
    float* part = reinterpret_cast<float*>(sm + PART_OFF);   // alias of ring
    float* slot = reinterpret_cast<float*>(sm + SLOT_OFF);
    float* vacc = reinterpret_cast<float*>(sm + VACC_OFF);
    unsigned int* vh = reinterpret_cast<unsigned int*>(sm + VH_OFF);

    const int tid = threadIdx.x;
    const int w = tid >> 5;
    const int l = tid & 31;
    const int rowl = l >> 2;      // row within chunk (0..7)
    const int q = l & 3;
    const int h = q & 1;          // o-half
    const int c0 = q >> 1;        // capsule parity
    const int b = blockIdx.x >> 1;
    unsigned int rank;
    asm("mov.u32 %0, %%cluster_ctarank;" : "=r"(rank));

    // lane's 5 uint4 slots within a chunk: idx = rowl*20 + q + 4k
    const int lane_u4 = rowl * 20 + q;
    const unsigned int ring0 = (unsigned int)__cvta_generic_to_shared(ring);
    const unsigned int lane_b = (unsigned int)(w * 160 + lane_u4) * 16;

    // v addresses: k-th capsule c=c0+2k, half h -> vh half2 index (c*8 + h*4)
    unsigned int vaddr[5];
#pragma unroll
    for (int k = 0; k < 5; k++)
        vaddr[k] = (unsigned int)__cvta_generic_to_shared(&vh[(c0 + 2 * k) * 8 + h * 4]);

    const uint4* ubase = g_uhat4 + ((size_t)b * RR + rank * (HALFCH * CHUNK)) * (CO / 8);

    for (int round = 0; round < 3; round++) {
        __half2 acc[5][4];
        const __half2 hz = __float2half2_rn(0.0f);
#pragma unroll
        for (int k = 0; k < 5; k++)
#pragma unroll
            for (int kk = 0; kk < 4; kk++) acc[k][kk] = hz;

        // prologue: stages 0..1 <- chunks 0..1
#pragma unroll
        for (int pf = 0; pf < 2; pf++) {
            const uint4* src = ubase + (w + pf * 8) * (CHUNK * CO / 8) + lane_u4;
            unsigned int dst = ring0 + pf * STAGE_B + lane_b;
#pragma unroll
            for (int k = 0; k < 5; k++) cp16(dst + k * 64, src + 4 * k);
            cp_commit();
        }

#pragma unroll
        for (int it = 0; it < ITERS2; it++) {  // 9, fully unrolled
            const int stage = it & 1;          // compile-time
            cp_wait1();

            uint4 uu[5];
            const uint4* rs = ring + stage * 1280 + (w * 160 + lane_u4);
#pragma unroll
            for (int k = 0; k < 5; k++) uu[k] = rs[4 * k];

            __half2 wgt2[5];
            if (round > 0) {
                float e[5];
#pragma unroll
                for (int k = 0; k < 5; k++) {
                    unsigned int v0r, v1r, v2r, v3r;
                    asm volatile("ld.shared.v4.b32 {%0,%1,%2,%3},[%4];"
                                 : "=r"(v0r), "=r"(v1r), "=r"(v2r), "=r"(v3r)
                                 : "r"(vaddr[k]));
                    const __half2* u2 = reinterpret_cast<const __half2*>(&uu[k]);
                    __half2 p2 = __hmul2(u2[0], *reinterpret_cast<__half2*>(&v0r));
                    p2 = __hfma2(u2[1], *reinterpret_cast<__half2*>(&v1r), p2);
                    p2 = __hfma2(u2[2], *reinterpret_cast<__half2*>(&v2r), p2);
                    p2 = __hfma2(u2[3], *reinterpret_cast<__half2*>(&v3r), p2);
                    float own = __low2float(p2) + __high2float(p2);
                    // join o-halves: partner lane l^1 has same capsule, other half
                    float lg = own + __shfl_xor_sync(0xffffffffu, own, 1);
                    e[k] = __expf(lg);  // logits bounded; no max-sub needed
                }
                // softmax over 10 capsules: own 5 (same parity) + partner parity
                float s5 = e[0] + e[1] + e[2] + e[3] + e[4];
                float tot = s5 + __shfl_xor_sync(0xffffffffu, s5, 2);
                float inv = 1.0f / tot;
#pragma unroll
                for (int k = 0; k < 5; k++)
                    wgt2[k] = __half2half2(__float2half_rn(e[k] * inv));
            }

#pragma unroll
            for (int k = 0; k < 5; k++) {
                const __half2* u2 = reinterpret_cast<const __half2*>(&uu[k]);
                if (round == 0) {
#pragma unroll
                    for (int kk = 0; kk < 4; kk++) acc[k][kk] = __hadd2(acc[k][kk], u2[kk]);
                } else {
#pragma unroll
                    for (int kk = 0; kk < 4; kk++) acc[k][kk] = __hfma2(u2[kk], wgt2[k], acc[k][kk]);
                }
            }

            // refill this stage with chunk it+2 (compile-time guard)
            if (it + 2 < ITERS2) {
                const uint4* src = ubase + (w + (it + 2) * 8) * (CHUNK * CO / 8) + lane_u4;
                unsigned int dst = ring0 + stage * STAGE_B + lane_b;
#pragma unroll
                for (int k = 0; k < 5; k++) cp16(dst + k * 64, src + 4 * k);
            }
            cp_commit();
        }

        // all warps done with ring reads before part (ring alias) is written
        __syncthreads();

        // flush fp16 accumulator to f32 partials (once per round)
        // lane owns co = (c0+2k)*16 + h*8 + [0,8)
#pragma unroll
        for (int k = 0; k < 5; k++) {
            float* pj = part + (w * 8 + rowl) * CO + (c0 + 2 * k) * 16 + h * 8;
#pragma unroll
            for (int kk = 0; kk < 4; kk++) {
                float2 fa = __half22float2(acc[k][kk]);
                pj[2 * kk]     = fa.x;
                pj[2 * kk + 1] = fa.y;
            }
        }
        __syncthreads();

        const int buf = round & 1;
        if (tid < CO) {
            float s = 0.0f;
#pragma unroll
            for (int i = 0; i < 64; i++) s += part[i * CO + tid];
            slot[(buf * 2 + rank) * CO + tid] = s;  // local copy
            unsigned int laddr = (unsigned int)__cvta_generic_to_shared(&slot[(buf * 2 + rank) * CO + tid]);
            st_peer_f32(laddr, rank ^ 1u, s);       // peer copy
        }
        asm volatile("barrier.cluster.arrive.aligned;" ::: "memory");
        asm volatile("barrier.cluster.wait.aligned;" ::: "memory");

        if (tid < CO) {
            float s = slot[(buf * 2 + 0) * CO + tid] + slot[(buf * 2 + 1) * CO + tid];
            if (round == 0) s *= 0.1f;  // softmax(0) = 1/10 exactly
            s += bias[tid];
            part[tid] = s;
        }
        __syncthreads();

        if (tid < CO) {
            int c = tid >> 4;
            float nsq = 0.0f;
#pragma unroll
            for (int o = 0; o < OO; o++) {
                float t = part[c * OO + o];
                nsq += t * t;
            }
            float val = part[tid] * (sqrtf(nsq) / (1.0f + nsq + 1e-8f));
            if (round == 0) vacc[tid] = val;                 // v0
            else if (round == 1) vacc[tid] += val;           // v0 + v1
            else if (rank == 0) dout[b * CO + tid] = val;    // v2 (final)
        }
        __syncthreads();

        if (round < 2 && tid < 80) {
            __half2 hv = __floats2half2_rn(vacc[2 * tid], vacc[2 * tid + 1]);
            vh[tid] = *reinterpret_cast<unsigned int*>(&hv);
        }
        __syncthreads();
    }
}

// ---------------------------------------------------------------------------
extern "C" void kernel_launch(void* const* d_in, const int* in_sizes, int n_in,
                              void* d_out, int out_size) {
    const float* x    = (const float*)d_in[0];  // [512,1152,8]
    const float* W    = (const float*)d_in[1];  // [1152,10,16,8]
    const float* bias = (const float*)d_in[2];  // [1,1,10,16]
    float* out = (float*)d_out;                 // [512,10,16]

    cudaFuncSetAttribute(route3_kernel, cudaFuncAttributeMaxDynamicSharedMemorySize, SMEM_BYTES);

    uhat_kernel<<<RR, 256>>>(x, W);
    route3_kernel<<<BB * 2, 256, SMEM_BYTES>>>(bias, out);
}